// round 1
// baseline (speedup 1.0000x reference)
#include <cuda_runtime.h>
#include <cuda_bf16.h>

#define BATCH 512
#define LSEQ 41
#define DMODEL 64
#define DINNER 128
#define NSTATE 16
#define DTRANK 4
#define KCONV 4
#define NSTACK 3
#define NLAYER 3
#define TP 50    /* padded t stride (even, 2-way-conflict rows) */
#define TPAD 48  /* padded t count */

__device__ float g_stack[(size_t)NSTACK * BATCH * LSEQ * DMODEL];
__device__ float g_h1[(size_t)BATCH * 384];

__device__ __forceinline__ void ffma2(unsigned long long& d, unsigned long long a, unsigned long long b) {
    asm("fma.rn.f32x2 %0, %1, %2, %0;" : "+l"(d) : "l"(a), "l"(b));
}
__device__ __forceinline__ unsigned long long pack2(float x) {
    unsigned long long r; asm("mov.b64 %0, {%1, %1};" : "=l"(r) : "f"(x)); return r;
}
__device__ __forceinline__ void unpack2(unsigned long long v, float& x, float& y) {
    asm("mov.b64 {%0, %1}, %2;" : "=f"(x), "=f"(y) : "l"(v));
}
__device__ __forceinline__ float siluf(float x) { return x / (1.f + __expf(-x)); }

extern "C" __global__ void __launch_bounds__(128, 2)
mamba_stack_kernel(const int* __restrict__ input_ids,
                   const float* __restrict__ embedding,
                   const float* __restrict__ in_proj,
                   const float* __restrict__ conv_w,
                   const float* __restrict__ conv_b,
                   const float* __restrict__ x_proj,
                   const float* __restrict__ dt_w,
                   const float* __restrict__ dt_b,
                   const float* __restrict__ A_log,
                   const float* __restrict__ Dp,
                   const float* __restrict__ out_proj,
                   const float* __restrict__ norm_w,
                   const float* __restrict__ norm_f_w)
{
    extern __shared__ float sm[];
    float* s_x    = sm;                      // 2624
    float* s_xnT  = s_x    + LSEQ*DMODEL;    // 64*50  = 3200
    float* s_uT   = s_xnT  + DMODEL*TP;      // 128*50 = 6400
    float* s_resT = s_uT   + DINNER*TP;      // 128*50 = 6400
    float* s_dbl  = s_resT + DINNER*TP;      // 41*36  = 1476
    float* s_w    = s_dbl  + LSEQ*36;        // 4608

    const int tid = threadIdx.x;
    const int b = blockIdx.x, s = blockIdx.y;
    const int warp = tid >> 5, lane = tid & 31;

    // ---- embedding gather ----
    for (int i = tid; i < LSEQ*DMODEL; i += 128) {
        int t = i >> 6, d = i & 63;
        s_x[i] = embedding[input_ids[b*LSEQ + t]*DMODEL + d];
    }

    for (int l = 0; l < NLAYER; ++l) {
        const int wb = s*NLAYER + l;
        __syncthreads();

        // ---- rmsnorm -> xnT (transposed, zero-padded t>=41) ----
        {
            float nw0 = norm_w[wb*DMODEL + lane];
            float nw1 = norm_w[wb*DMODEL + 32 + lane];
            for (int t = warp; t < TPAD; t += 4) {
                if (t < LSEQ) {
                    float v0 = s_x[t*DMODEL + lane];
                    float v1 = s_x[t*DMODEL + 32 + lane];
                    float ss = v0*v0 + v1*v1;
                    #pragma unroll
                    for (int o = 16; o; o >>= 1) ss += __shfl_xor_sync(0xffffffffu, ss, o);
                    float inv = rsqrtf(ss * (1.f/64.f) + 1e-5f);
                    s_xnT[lane*TP + t]      = v0 * inv * nw0;
                    s_xnT[(lane+32)*TP + t] = v1 * inv * nw1;
                } else {
                    s_xnT[lane*TP + t] = 0.f;
                    s_xnT[(lane+32)*TP + t] = 0.f;
                }
            }
        }

        // ---- in_proj matmul: [41x64] @ [64x256] ; thread owns cols tid (u) and tid+128 (res) ----
        unsigned long long accU[24], accR[24];
        #pragma unroll
        for (int k = 0; k < 24; ++k) { accU[k] = 0ull; accR[k] = 0ull; }
        {
            const float* ipw = in_proj + (size_t)wb * DMODEL * 2 * DINNER;
            for (int dc = 0; dc < 4; ++dc) {
                __syncthreads();
                #pragma unroll
                for (int i = tid*4; i < 4096; i += 512)
                    *(float4*)&s_w[i] = *(const float4*)&ipw[dc*4096 + i];
                __syncthreads();
                #pragma unroll
                for (int dd = 0; dd < 16; ++dd) {
                    const int d = dc*16 + dd;
                    unsigned long long wu2 = pack2(s_w[dd*256 + tid]);
                    unsigned long long wr2 = pack2(s_w[dd*256 + 128 + tid]);
                    const unsigned long long* xr = (const unsigned long long*)&s_xnT[d*TP];
                    #pragma unroll
                    for (int k = 0; k < 24; ++k) {
                        unsigned long long xv = xr[k];
                        ffma2(accU[k], xv, wu2);
                        ffma2(accR[k], xv, wr2);
                    }
                }
            }
        }

        // ---- silu(res) store; causal conv(K=4)+bias+silu -> uT (thread = channel) ----
        {
            #pragma unroll
            for (int k = 0; k < 24; ++k) {
                float r0, r1; unpack2(accR[k], r0, r1);
                s_resT[tid*TP + 2*k]   = siluf(r0);
                s_resT[tid*TP + 2*k+1] = siluf(r1);
            }
            float ul[TPAD];
            #pragma unroll
            for (int k = 0; k < 24; ++k) unpack2(accU[k], ul[2*k], ul[2*k+1]);
            const float* cw = conv_w + (size_t)(wb*DINNER + tid)*KCONV;
            float c0 = cw[0], c1 = cw[1], c2 = cw[2], c3 = cw[3];
            float cb = conv_b[wb*DINNER + tid];
            #pragma unroll
            for (int t = 0; t < LSEQ; ++t) {
                float a = ul[t]*c3 + cb;
                if (t >= 1) a += ul[t-1]*c2;
                if (t >= 2) a += ul[t-2]*c1;
                if (t >= 3) a += ul[t-3]*c0;
                s_uT[tid*TP + t] = siluf(a);
            }
            #pragma unroll
            for (int t = LSEQ; t < TPAD; ++t) s_uT[tid*TP + t] = 0.f;
        }

        // ---- x_proj matmul: dbl[41][36] = u @ xp[128x36] ----
        {
            __syncthreads();
            const float* xpw = x_proj + (size_t)wb * DINNER * 36;
            for (int i = tid; i < DINNER*36; i += 128) s_w[i] = xpw[i];
            __syncthreads();
            const int jj = tid % 36;
            const int g  = tid / 36;
            if (g < 3) {
                const int t0 = g * 14;
                unsigned long long acc2[7];
                #pragma unroll
                for (int k = 0; k < 7; ++k) acc2[k] = 0ull;
                for (int d = 0; d < DINNER; ++d) {
                    unsigned long long w2 = pack2(s_w[d*36 + jj]);
                    const unsigned long long* ur = (const unsigned long long*)&s_uT[d*TP + t0];
                    #pragma unroll
                    for (int k = 0; k < 7; ++k) ffma2(acc2[k], ur[k], w2);
                }
                #pragma unroll
                for (int k = 0; k < 7; ++k) {
                    float a0, a1; unpack2(acc2[k], a0, a1);
                    int t = t0 + 2*k;
                    if (t < LSEQ)   s_dbl[t*36 + jj]     = a0;
                    if (t+1 < LSEQ) s_dbl[(t+1)*36 + jj] = a1;
                }
            }
        }

        // ---- selective scan (thread = channel, h[16] in regs) ----
        {
            float dw0 = dt_w[(wb*DTRANK+0)*DINNER + tid];
            float dw1 = dt_w[(wb*DTRANK+1)*DINNER + tid];
            float dw2 = dt_w[(wb*DTRANK+2)*DINNER + tid];
            float dw3 = dt_w[(wb*DTRANK+3)*DINNER + tid];
            float dtbv = dt_b[wb*DINNER + tid];
            float dpv  = Dp[wb*DINNER + tid];
            float Av[NSTATE];
            const float* al = A_log + (size_t)(wb*DINNER + tid)*NSTATE;
            #pragma unroll
            for (int n = 0; n < NSTATE; ++n) Av[n] = -__expf(al[n]);
            __syncthreads();
            float h[NSTATE];
            #pragma unroll
            for (int n = 0; n < NSTATE; ++n) h[n] = 0.f;
            for (int t = 0; t < LSEQ; ++t) {
                const float* dr = &s_dbl[t*36];
                float xr = dr[0]*dw0 + dr[1]*dw1 + dr[2]*dw2 + dr[3]*dw3 + dtbv;
                float dt = (xr > 15.f) ? xr : log1pf(__expf(xr));
                float ut = s_uT[tid*TP + t];
                float dtu = dt * ut;
                float y = 0.f;
                #pragma unroll
                for (int n = 0; n < NSTATE; ++n) {
                    float dA = __expf(dt * Av[n]);
                    h[n] = dA*h[n] + dtu*dr[4+n];
                    y += h[n]*dr[20+n];
                }
                // gate: (y + u*Dp) * silu(res); overwrite uT in place
                s_uT[tid*TP + t] = (y + ut*dpv) * s_resT[tid*TP + t];
            }
        }

        // ---- out_proj matmul + residual add: x += g @ op[128x64] ----
        {
            const float* opw = out_proj + (size_t)wb * DINNER * DMODEL;
            const int col = tid & 63;
            const int th  = tid >> 6;   // t-halves 0..23 / 24..47
            unsigned long long acc2[12];
            #pragma unroll
            for (int k = 0; k < 12; ++k) acc2[k] = 0ull;
            for (int dc = 0; dc < 2; ++dc) {
                __syncthreads();
                #pragma unroll
                for (int i = tid*4; i < 4096; i += 512)
                    *(float4*)&s_w[i] = *(const float4*)&opw[dc*4096 + i];
                __syncthreads();
                #pragma unroll
                for (int dd = 0; dd < 64; ++dd) {
                    const int d = dc*64 + dd;
                    unsigned long long w2 = pack2(s_w[dd*64 + col]);
                    const unsigned long long* gr = (const unsigned long long*)&s_uT[d*TP + th*24];
                    #pragma unroll
                    for (int k = 0; k < 12; ++k) ffma2(acc2[k], gr[k], w2);
                }
            }
            __syncthreads();
            #pragma unroll
            for (int k = 0; k < 12; ++k) {
                float a0, a1; unpack2(acc2[k], a0, a1);
                int t = th*24 + 2*k;
                if (t < LSEQ)   s_x[t*DMODEL + col]     += a0;
                if (t+1 < LSEQ) s_x[(t+1)*DMODEL + col] += a1;
            }
        }
    }

    // ---- final rmsnorm (norm_f_w) + store stack output ----
    __syncthreads();
    {
        float nw0 = norm_f_w[lane], nw1 = norm_f_w[32 + lane];
        for (int t = warp; t < LSEQ; t += 4) {
            float v0 = s_x[t*DMODEL + lane];
            float v1 = s_x[t*DMODEL + 32 + lane];
            float ss = v0*v0 + v1*v1;
            #pragma unroll
            for (int o = 16; o; o >>= 1) ss += __shfl_xor_sync(0xffffffffu, ss, o);
            float inv = rsqrtf(ss * (1.f/64.f) + 1e-5f);
            float* dst = g_stack + ((size_t)(s*BATCH + b)*LSEQ + t)*DMODEL;
            dst[lane]      = v0 * inv * nw0;
            dst[lane + 32] = v1 * inv * nw1;
        }
    }
}

// ---- head GEMM: h1 = relu(fused[512x2624] @ W1[2624x384] + b1), fused = softmax(fw)·stacks ----
__global__ void __launch_bounds__(128)
head_gemm1(const float* __restrict__ fusion_w, const float* __restrict__ W1,
           const float* __restrict__ b1)
{
    __shared__ float As[32][33];
    __shared__ float Ws[32][64];
    const int tid = threadIdx.x;
    const int rb = blockIdx.x, cb = blockIdx.y;
    float f0 = fusion_w[0], f1 = fusion_w[1], f2 = fusion_w[2];
    float m = fmaxf(f0, fmaxf(f1, f2));
    float e0 = expf(f0-m), e1 = expf(f1-m), e2 = expf(f2-m);
    float inv = 1.f/(e0+e1+e2);
    e0 *= inv; e1 *= inv; e2 *= inv;
    const int tx = tid & 15, ty = tid >> 4;
    float acc[4][4];
    #pragma unroll
    for (int r = 0; r < 4; ++r)
        #pragma unroll
        for (int c = 0; c < 4; ++c) acc[r][c] = 0.f;
    const int KT = LSEQ*DMODEL;             // 2624 = 82*32
    const size_t SS = (size_t)BATCH * KT;   // stack stride
    for (int kc = 0; kc < KT/32; ++kc) {
        __syncthreads();
        #pragma unroll
        for (int i = tid; i < 1024; i += 128) {
            int r = i >> 5, kk = i & 31;
            size_t base = (size_t)(rb*32 + r)*KT + kc*32 + kk;
            As[r][kk] = e0*g_stack[base] + e1*g_stack[base + SS] + e2*g_stack[base + 2*SS];
        }
        #pragma unroll
        for (int i = tid; i < 2048; i += 128) {
            int kk = i >> 6, j = i & 63;
            Ws[kk][j] = W1[(size_t)(kc*32 + kk)*384 + cb*64 + j];
        }
        __syncthreads();
        #pragma unroll
        for (int kk = 0; kk < 32; ++kk) {
            float a0 = As[ty*4+0][kk], a1 = As[ty*4+1][kk];
            float a2 = As[ty*4+2][kk], a3 = As[ty*4+3][kk];
            float4 w = *(const float4*)&Ws[kk][tx*4];
            acc[0][0] += a0*w.x; acc[0][1] += a0*w.y; acc[0][2] += a0*w.z; acc[0][3] += a0*w.w;
            acc[1][0] += a1*w.x; acc[1][1] += a1*w.y; acc[1][2] += a1*w.z; acc[1][3] += a1*w.w;
            acc[2][0] += a2*w.x; acc[2][1] += a2*w.y; acc[2][2] += a2*w.z; acc[2][3] += a2*w.w;
            acc[3][0] += a3*w.x; acc[3][1] += a3*w.y; acc[3][2] += a3*w.z; acc[3][3] += a3*w.w;
        }
    }
    #pragma unroll
    for (int r = 0; r < 4; ++r) {
        int row = rb*32 + ty*4 + r;
        #pragma unroll
        for (int c = 0; c < 4; ++c) {
            int colg = cb*64 + tx*4 + c;
            g_h1[(size_t)row*384 + colg] = fmaxf(acc[r][c] + b1[colg], 0.f);
        }
    }
}

// ---- final tail: h2 = relu(h1 @ W2 + b2); logit = h2 @ W3 + b3; sigmoid ----
__global__ void head_final(const float* __restrict__ W2, const float* __restrict__ b2,
                           const float* __restrict__ W3, const float* __restrict__ b3,
                           float* __restrict__ out)
{
    const int warp = threadIdx.x >> 5, lane = threadIdx.x & 31;
    const int b = blockIdx.x*4 + warp;
    if (b >= BATCH) return;
    const int j = lane & 15;
    const float* hr = g_h1 + (size_t)b*384;
    float a0 = 0.f, a1 = 0.f, a2 = 0.f, a3 = 0.f;
    for (int i = 0; i < 384; i += 4) {
        a0 += hr[i]   * W2[(i  )*16 + j];
        a1 += hr[i+1] * W2[(i+1)*16 + j];
        a2 += hr[i+2] * W2[(i+2)*16 + j];
        a3 += hr[i+3] * W2[(i+3)*16 + j];
    }
    float h2 = fmaxf(a0 + a1 + a2 + a3 + b2[j], 0.f);
    float p = (lane < 16) ? h2 * W3[j] : 0.f;
    #pragma unroll
    for (int o = 16; o; o >>= 1) p += __shfl_xor_sync(0xffffffffu, p, o);
    if (lane == 0) out[b] = 1.f / (1.f + expf(-(p + b3[0])));
}

extern "C" void kernel_launch(void* const* d_in, const int* in_sizes, int n_in,
                              void* d_out, int out_size) {
    const int*   input_ids = (const int*)d_in[0];
    const float* embedding = (const float*)d_in[1];
    const float* in_proj   = (const float*)d_in[2];
    const float* conv_w    = (const float*)d_in[3];
    const float* conv_b    = (const float*)d_in[4];
    const float* x_proj    = (const float*)d_in[5];
    const float* dt_w      = (const float*)d_in[6];
    const float* dt_b      = (const float*)d_in[7];
    const float* A_log     = (const float*)d_in[8];
    const float* Dp        = (const float*)d_in[9];
    const float* out_proj  = (const float*)d_in[10];
    const float* norm_w    = (const float*)d_in[11];
    const float* norm_f_w  = (const float*)d_in[12];
    const float* fusion_w  = (const float*)d_in[13];
    const float* W1        = (const float*)d_in[14];
    const float* b1        = (const float*)d_in[15];
    const float* W2        = (const float*)d_in[16];
    const float* b2        = (const float*)d_in[17];
    const float* W3        = (const float*)d_in[18];
    const float* b3        = (const float*)d_in[19];
    float* out = (float*)d_out;
    (void)in_sizes; (void)n_in; (void)out_size;

    const int smemA = 24708 * 4;  // 98832 bytes
    cudaFuncSetAttribute(mamba_stack_kernel,
                         cudaFuncAttributeMaxDynamicSharedMemorySize, smemA);
    mamba_stack_kernel<<<dim3(BATCH, NSTACK), 128, smemA>>>(
        input_ids, embedding, in_proj, conv_w, conv_b, x_proj, dt_w, dt_b,
        A_log, Dp, out_proj, norm_w, norm_f_w);
    head_gemm1<<<dim3(16, 6), 128>>>(fusion_w, W1, b1);
    head_final<<<128, 128>>>(W2, b2, W3, b3, out);
}

// round 2
// speedup vs baseline: 1.2110x; 1.2110x over previous
#include <cuda_runtime.h>
#include <cuda_bf16.h>

#define BATCH 512
#define LSEQ 41
#define DMODEL 64
#define DINNER 128
#define NSTATE 16
#define DTRANK 4
#define KCONV 4
#define NSTACK 3
#define NLAYER 3
#define TP 46    /* padded t row stride (even for 8B ULL, 2-way-conflict rows) */
#define TPAD 44  /* padded t count actually used (22 f32x2 pairs) */
#define NPAIR 22

__device__ float g_stack[(size_t)NSTACK * BATCH * LSEQ * DMODEL];
__device__ float g_h1[(size_t)BATCH * 384];

__device__ __forceinline__ void ffma2(unsigned long long& d, unsigned long long a, unsigned long long b) {
    asm("fma.rn.f32x2 %0, %1, %2, %0;" : "+l"(d) : "l"(a), "l"(b));
}
__device__ __forceinline__ unsigned long long pack2(float x) {
    unsigned long long r; asm("mov.b64 %0, {%1, %1};" : "=l"(r) : "f"(x)); return r;
}
__device__ __forceinline__ void unpack2(unsigned long long v, float& x, float& y) {
    asm("mov.b64 {%0, %1}, %2;" : "=f"(x), "=f"(y) : "l"(v));
}
__device__ __forceinline__ float siluf(float x) { return x / (1.f + __expf(-x)); }

extern "C" __global__ void __launch_bounds__(128, 3)
mamba_stack_kernel(const int* __restrict__ input_ids,
                   const float* __restrict__ embedding,
                   const float* __restrict__ in_proj,
                   const float* __restrict__ conv_w,
                   const float* __restrict__ conv_b,
                   const float* __restrict__ x_proj,
                   const float* __restrict__ dt_w,
                   const float* __restrict__ dt_b,
                   const float* __restrict__ A_log,
                   const float* __restrict__ Dp,
                   const float* __restrict__ out_proj,
                   const float* __restrict__ norm_w,
                   const float* __restrict__ norm_f_w)
{
    extern __shared__ float sm[];
    float* s_x    = sm;                      // 41*64 = 2624
    float* s_xnT  = s_x    + LSEQ*DMODEL;    // 64*46 = 2944
    float* s_uT   = s_xnT  + DMODEL*TP;      // 128*46 = 5888
    float* s_dbl  = s_uT   + DINNER*TP;      // 41*36  = 1476
    float* s_w    = s_dbl  + LSEQ*36;        // 4608
    // total 17540 floats = 70160 bytes -> 3 CTAs/SM

    const int tid = threadIdx.x;
    const int b = blockIdx.x, s = blockIdx.y;
    const int warp = tid >> 5, lane = tid & 31;

    // ---- embedding gather ----
    for (int i = tid; i < LSEQ*DMODEL; i += 128) {
        int t = i >> 6, d = i & 63;
        s_x[i] = embedding[input_ids[b*LSEQ + t]*DMODEL + d];
    }

    for (int l = 0; l < NLAYER; ++l) {
        const int wb = s*NLAYER + l;
        __syncthreads();

        // ---- rmsnorm -> xnT (transposed, zero-padded t>=41) ----
        {
            float nw0 = norm_w[wb*DMODEL + lane];
            float nw1 = norm_w[wb*DMODEL + 32 + lane];
            for (int t = warp; t < TPAD; t += 4) {
                if (t < LSEQ) {
                    float v0 = s_x[t*DMODEL + lane];
                    float v1 = s_x[t*DMODEL + 32 + lane];
                    float ss = v0*v0 + v1*v1;
                    #pragma unroll
                    for (int o = 16; o; o >>= 1) ss += __shfl_xor_sync(0xffffffffu, ss, o);
                    float inv = rsqrtf(ss * (1.f/64.f) + 1e-5f);
                    s_xnT[lane*TP + t]      = v0 * inv * nw0;
                    s_xnT[(lane+32)*TP + t] = v1 * inv * nw1;
                } else {
                    s_xnT[lane*TP + t] = 0.f;
                    s_xnT[(lane+32)*TP + t] = 0.f;
                }
            }
        }

        // ---- in_proj matmul: [41x64] @ [64x256] ; thread owns col tid (u) and tid+128 (res) ----
        // accR stays in registers through conv/x_proj/scan; gating applied after scan.
        unsigned long long accR[NPAIR];
        {
            unsigned long long accU[NPAIR];
            #pragma unroll
            for (int k = 0; k < NPAIR; ++k) { accU[k] = 0ull; accR[k] = 0ull; }
            const float* ipw = in_proj + (size_t)wb * DMODEL * 2 * DINNER;
            for (int dc = 0; dc < 4; ++dc) {
                __syncthreads();
                #pragma unroll
                for (int i = tid*4; i < 4096; i += 512)
                    *(float4*)&s_w[i] = *(const float4*)&ipw[dc*4096 + i];
                __syncthreads();
                #pragma unroll
                for (int dd = 0; dd < 16; ++dd) {
                    const int d = dc*16 + dd;
                    unsigned long long wu2 = pack2(s_w[dd*256 + tid]);
                    unsigned long long wr2 = pack2(s_w[dd*256 + 128 + tid]);
                    const unsigned long long* xr = (const unsigned long long*)&s_xnT[d*TP];
                    #pragma unroll
                    for (int k = 0; k < NPAIR; ++k) {
                        unsigned long long xv = xr[k];
                        ffma2(accU[k], xv, wu2);
                        ffma2(accR[k], xv, wr2);
                    }
                }
            }

            // ---- causal conv(K=4)+bias+silu -> uT (thread = channel) ----
            float ul[TPAD];
            #pragma unroll
            for (int k = 0; k < NPAIR; ++k) unpack2(accU[k], ul[2*k], ul[2*k+1]);
            const float* cw = conv_w + (size_t)(wb*DINNER + tid)*KCONV;
            float c0 = cw[0], c1 = cw[1], c2 = cw[2], c3 = cw[3];
            float cb = conv_b[wb*DINNER + tid];
            #pragma unroll
            for (int t = 0; t < LSEQ; ++t) {
                float a = ul[t]*c3 + cb;
                if (t >= 1) a += ul[t-1]*c2;
                if (t >= 2) a += ul[t-2]*c1;
                if (t >= 3) a += ul[t-3]*c0;
                s_uT[tid*TP + t] = siluf(a);
            }
            #pragma unroll
            for (int t = LSEQ; t < TPAD; ++t) s_uT[tid*TP + t] = 0.f;
        }

        // ---- x_proj matmul: dbl[41][36] = u @ xp[128x36] ----
        {
            __syncthreads();
            const float* xpw = x_proj + (size_t)wb * DINNER * 36;
            #pragma unroll
            for (int i = tid*4; i < DINNER*36; i += 512)
                *(float4*)&s_w[i] = *(const float4*)&xpw[i];
            __syncthreads();
            const int jj = tid % 36;
            const int g  = tid / 36;
            if (g < 3) {
                const int t0 = g * 14;
                unsigned long long acc2[7];
                #pragma unroll
                for (int k = 0; k < 7; ++k) acc2[k] = 0ull;
                for (int d = 0; d < DINNER; ++d) {
                    unsigned long long w2 = pack2(s_w[d*36 + jj]);
                    const unsigned long long* ur = (const unsigned long long*)&s_uT[d*TP + t0];
                    #pragma unroll
                    for (int k = 0; k < 7; ++k) ffma2(acc2[k], ur[k], w2);
                }
                #pragma unroll
                for (int k = 0; k < 7; ++k) {
                    float a0, a1; unpack2(acc2[k], a0, a1);
                    int t = t0 + 2*k;
                    if (t < LSEQ)   s_dbl[t*36 + jj]     = a0;
                    if (t+1 < LSEQ) s_dbl[(t+1)*36 + jj] = a1;
                }
            }
        }

        // ---- selective scan (thread = channel, h[16] in regs) ----
        {
            float dw0 = dt_w[(wb*DTRANK+0)*DINNER + tid];
            float dw1 = dt_w[(wb*DTRANK+1)*DINNER + tid];
            float dw2 = dt_w[(wb*DTRANK+2)*DINNER + tid];
            float dw3 = dt_w[(wb*DTRANK+3)*DINNER + tid];
            float dtbv = dt_b[wb*DINNER + tid];
            float dpv  = Dp[wb*DINNER + tid];
            float Av[NSTATE];
            const float* al = A_log + (size_t)(wb*DINNER + tid)*NSTATE;
            #pragma unroll
            for (int n = 0; n < NSTATE; ++n) Av[n] = -__expf(al[n]);
            __syncthreads();
            float h[NSTATE];
            #pragma unroll
            for (int n = 0; n < NSTATE; ++n) h[n] = 0.f;
            for (int t = 0; t < LSEQ; ++t) {
                const float* dr = &s_dbl[t*36];
                float xr = dr[0]*dw0 + dr[1]*dw1 + dr[2]*dw2 + dr[3]*dw3 + dtbv;
                float dt = (xr > 15.f) ? xr : log1pf(__expf(xr));
                float ut = s_uT[tid*TP + t];
                float dtu = dt * ut;
                float y = 0.f;
                #pragma unroll
                for (int n = 0; n < NSTATE; ++n) {
                    float dA = __expf(dt * Av[n]);
                    h[n] = dA*h[n] + dtu*dr[4+n];
                    y += h[n]*dr[20+n];
                }
                // store ungated z_t = y + u*Dp; gating applied below from accR
                s_uT[tid*TP + t] = y + ut*dpv;
            }
        }

        // ---- gate with silu(res) held in registers (thread owns its channel row) ----
        {
            #pragma unroll
            for (int k = 0; k < NPAIR; ++k) {
                float r0, r1; unpack2(accR[k], r0, r1);
                s_uT[tid*TP + 2*k]   *= siluf(r0);
                s_uT[tid*TP + 2*k+1] *= siluf(r1);
            }
        }

        // ---- out_proj matmul + residual add: x += g @ op[128x64] ----
        {
            const float* opw = out_proj + (size_t)wb * DINNER * DMODEL;
            const int col = tid & 63;
            const int th  = tid >> 6;   // t-halves: pairs [0,11) / [11,22)
            unsigned long long acc2[11];
            #pragma unroll
            for (int k = 0; k < 11; ++k) acc2[k] = 0ull;
            for (int dc = 0; dc < 2; ++dc) {
                __syncthreads();
                #pragma unroll
                for (int i = tid*4; i < 4096; i += 512)
                    *(float4*)&s_w[i] = *(const float4*)&opw[dc*4096 + i];
                __syncthreads();
                #pragma unroll
                for (int dd = 0; dd < 64; ++dd) {
                    const int d = dc*64 + dd;
                    unsigned long long w2 = pack2(s_w[dd*64 + col]);
                    const unsigned long long* gr = (const unsigned long long*)&s_uT[d*TP + th*22];
                    #pragma unroll
                    for (int k = 0; k < 11; ++k) ffma2(acc2[k], gr[k], w2);
                }
            }
            __syncthreads();
            #pragma unroll
            for (int k = 0; k < 11; ++k) {
                float a0, a1; unpack2(acc2[k], a0, a1);
                int t = th*22 + 2*k;
                if (t < LSEQ)   s_x[t*DMODEL + col]     += a0;
                if (t+1 < LSEQ) s_x[(t+1)*DMODEL + col] += a1;
            }
        }
    }

    // ---- final rmsnorm (norm_f_w) + store stack output ----
    __syncthreads();
    {
        float nw0 = norm_f_w[lane], nw1 = norm_f_w[32 + lane];
        for (int t = warp; t < LSEQ; t += 4) {
            float v0 = s_x[t*DMODEL + lane];
            float v1 = s_x[t*DMODEL + 32 + lane];
            float ss = v0*v0 + v1*v1;
            #pragma unroll
            for (int o = 16; o; o >>= 1) ss += __shfl_xor_sync(0xffffffffu, ss, o);
            float inv = rsqrtf(ss * (1.f/64.f) + 1e-5f);
            float* dst = g_stack + ((size_t)(s*BATCH + b)*LSEQ + t)*DMODEL;
            dst[lane]      = v0 * inv * nw0;
            dst[lane + 32] = v1 * inv * nw1;
        }
    }
}

// ---- head GEMM: h1 = relu(fused[512x2624] @ W1[2624x384] + b1), fused = softmax(fw)·stacks ----
__global__ void __launch_bounds__(128)
head_gemm1(const float* __restrict__ fusion_w, const float* __restrict__ W1,
           const float* __restrict__ b1)
{
    __shared__ float As[32][33];
    __shared__ float Ws[32][64];
    const int tid = threadIdx.x;
    const int rb = blockIdx.x, cb = blockIdx.y;
    float f0 = fusion_w[0], f1 = fusion_w[1], f2 = fusion_w[2];
    float m = fmaxf(f0, fmaxf(f1, f2));
    float e0 = expf(f0-m), e1 = expf(f1-m), e2 = expf(f2-m);
    float inv = 1.f/(e0+e1+e2);
    e0 *= inv; e1 *= inv; e2 *= inv;
    const int tx = tid & 15, ty = tid >> 4;
    float acc[4][4];
    #pragma unroll
    for (int r = 0; r < 4; ++r)
        #pragma unroll
        for (int c = 0; c < 4; ++c) acc[r][c] = 0.f;
    const int KT = LSEQ*DMODEL;             // 2624 = 82*32
    const size_t SS = (size_t)BATCH * KT;   // stack stride
    for (int kc = 0; kc < KT/32; ++kc) {
        __syncthreads();
        #pragma unroll
        for (int i = tid; i < 1024; i += 128) {
            int r = i >> 5, kk = i & 31;
            size_t base = (size_t)(rb*32 + r)*KT + kc*32 + kk;
            As[r][kk] = e0*g_stack[base] + e1*g_stack[base + SS] + e2*g_stack[base + 2*SS];
        }
        #pragma unroll
        for (int i = tid; i < 2048; i += 128) {
            int kk = i >> 6, j = i & 63;
            Ws[kk][j] = W1[(size_t)(kc*32 + kk)*384 + cb*64 + j];
        }
        __syncthreads();
        #pragma unroll
        for (int kk = 0; kk < 32; ++kk) {
            float a0 = As[ty*4+0][kk], a1 = As[ty*4+1][kk];
            float a2 = As[ty*4+2][kk], a3 = As[ty*4+3][kk];
            float4 w = *(const float4*)&Ws[kk][tx*4];
            acc[0][0] += a0*w.x; acc[0][1] += a0*w.y; acc[0][2] += a0*w.z; acc[0][3] += a0*w.w;
            acc[1][0] += a1*w.x; acc[1][1] += a1*w.y; acc[1][2] += a1*w.z; acc[1][3] += a1*w.w;
            acc[2][0] += a2*w.x; acc[2][1] += a2*w.y; acc[2][2] += a2*w.z; acc[2][3] += a2*w.w;
            acc[3][0] += a3*w.x; acc[3][1] += a3*w.y; acc[3][2] += a3*w.z; acc[3][3] += a3*w.w;
        }
    }
    #pragma unroll
    for (int r = 0; r < 4; ++r) {
        int row = rb*32 + ty*4 + r;
        #pragma unroll
        for (int c = 0; c < 4; ++c) {
            int colg = cb*64 + tx*4 + c;
            g_h1[(size_t)row*384 + colg] = fmaxf(acc[r][c] + b1[colg], 0.f);
        }
    }
}

// ---- final tail: h2 = relu(h1 @ W2 + b2); logit = h2 @ W3 + b3; sigmoid ----
__global__ void head_final(const float* __restrict__ W2, const float* __restrict__ b2,
                           const float* __restrict__ W3, const float* __restrict__ b3,
                           float* __restrict__ out)
{
    const int warp = threadIdx.x >> 5, lane = threadIdx.x & 31;
    const int b = blockIdx.x*4 + warp;
    if (b >= BATCH) return;
    const int j = lane & 15;
    const float* hr = g_h1 + (size_t)b*384;
    float a0 = 0.f, a1 = 0.f, a2 = 0.f, a3 = 0.f;
    for (int i = 0; i < 384; i += 4) {
        a0 += hr[i]   * W2[(i  )*16 + j];
        a1 += hr[i+1] * W2[(i+1)*16 + j];
        a2 += hr[i+2] * W2[(i+2)*16 + j];
        a3 += hr[i+3] * W2[(i+3)*16 + j];
    }
    float h2 = fmaxf(a0 + a1 + a2 + a3 + b2[j], 0.f);
    float p = (lane < 16) ? h2 * W3[j] : 0.f;
    #pragma unroll
    for (int o = 16; o; o >>= 1) p += __shfl_xor_sync(0xffffffffu, p, o);
    if (lane == 0) out[b] = 1.f / (1.f + expf(-(p + b3[0])));
}

extern "C" void kernel_launch(void* const* d_in, const int* in_sizes, int n_in,
                              void* d_out, int out_size) {
    const int*   input_ids = (const int*)d_in[0];
    const float* embedding = (const float*)d_in[1];
    const float* in_proj   = (const float*)d_in[2];
    const float* conv_w    = (const float*)d_in[3];
    const float* conv_b    = (const float*)d_in[4];
    const float* x_proj    = (const float*)d_in[5];
    const float* dt_w      = (const float*)d_in[6];
    const float* dt_b      = (const float*)d_in[7];
    const float* A_log     = (const float*)d_in[8];
    const float* Dp        = (const float*)d_in[9];
    const float* out_proj  = (const float*)d_in[10];
    const float* norm_w    = (const float*)d_in[11];
    const float* norm_f_w  = (const float*)d_in[12];
    const float* fusion_w  = (const float*)d_in[13];
    const float* W1        = (const float*)d_in[14];
    const float* b1        = (const float*)d_in[15];
    const float* W2        = (const float*)d_in[16];
    const float* b2        = (const float*)d_in[17];
    const float* W3        = (const float*)d_in[18];
    const float* b3        = (const float*)d_in[19];
    float* out = (float*)d_out;
    (void)in_sizes; (void)n_in; (void)out_size;

    const int smemA = 17540 * 4;  // 70160 bytes -> 3 CTAs/SM
    cudaFuncSetAttribute(mamba_stack_kernel,
                         cudaFuncAttributeMaxDynamicSharedMemorySize, smemA);
    mamba_stack_kernel<<<dim3(BATCH, NSTACK), 128, smemA>>>(
        input_ids, embedding, in_proj, conv_w, conv_b, x_proj, dt_w, dt_b,
        A_log, Dp, out_proj, norm_w, norm_f_w);
    head_gemm1<<<dim3(16, 6), 128>>>(fusion_w, W1, b1);
    head_final<<<128, 128>>>(W2, b2, W3, b3, out);
}

// round 3
// speedup vs baseline: 1.2440x; 1.0272x over previous
#include <cuda_runtime.h>
#include <cuda_bf16.h>

#define BATCH 512
#define LSEQ 41
#define DMODEL 64
#define DINNER 128
#define NSTATE 16
#define DTRANK 4
#define KCONV 4
#define NSTACK 3
#define NLAYER 3
#define TP 46    /* padded t row stride (even for 8B ULL, 2-way-conflict rows) */
#define TPAD 44  /* padded t count actually used (22 f32x2 pairs) */
#define NPAIR 22

typedef unsigned long long ULL;

__device__ float g_stack[(size_t)NSTACK * BATCH * LSEQ * DMODEL];
__device__ float g_h1[(size_t)BATCH * 384];

__device__ __forceinline__ void ffma2(ULL& d, ULL a, ULL b) {
    asm("fma.rn.f32x2 %0, %1, %2, %0;" : "+l"(d) : "l"(a), "l"(b));
}
__device__ __forceinline__ ULL pack2(float x) {
    ULL r; asm("mov.b64 %0, {%1, %1};" : "=l"(r) : "f"(x)); return r;
}
__device__ __forceinline__ ULL pack2f(float lo, float hi) {
    ULL r; asm("mov.b64 %0, {%1, %2};" : "=l"(r) : "f"(lo), "f"(hi)); return r;
}
__device__ __forceinline__ ULL mul2(ULL a, ULL b) {
    ULL r; asm("mul.rn.f32x2 %0, %1, %2;" : "=l"(r) : "l"(a), "l"(b)); return r;
}
__device__ __forceinline__ void unpack2(ULL v, float& x, float& y) {
    asm("mov.b64 {%0, %1}, %2;" : "=f"(x), "=f"(y) : "l"(v));
}
__device__ __forceinline__ float siluf(float x) { return x / (1.f + __expf(-x)); }

extern "C" __global__ void __launch_bounds__(128, 3)
mamba_stack_kernel(const int* __restrict__ input_ids,
                   const float* __restrict__ embedding,
                   const float* __restrict__ in_proj,
                   const float* __restrict__ conv_w,
                   const float* __restrict__ conv_b,
                   const float* __restrict__ x_proj,
                   const float* __restrict__ dt_w,
                   const float* __restrict__ dt_b,
                   const float* __restrict__ A_log,
                   const float* __restrict__ Dp,
                   const float* __restrict__ out_proj,
                   const float* __restrict__ norm_w,
                   const float* __restrict__ norm_f_w)
{
    extern __shared__ float sm[];
    float* s_x    = sm;                      // 41*64 = 2624
    float* s_xnT  = s_x    + LSEQ*DMODEL;    // 64*46 = 2944
    float* s_uT   = s_xnT  + DMODEL*TP;      // 128*46 = 5888
    float* s_dbl  = s_uT   + DINNER*TP;      // 41*36  = 1476
    float* s_w    = s_dbl  + LSEQ*36;        // 4608
    // total 17540 floats = 70160 bytes -> 3 CTAs/SM

    const int tid = threadIdx.x;
    const int b = blockIdx.x, s = blockIdx.y;
    const int warp = tid >> 5, lane = tid & 31;
    const int cI = tid & 63;        // in_proj col group
    const int hI = tid >> 6;        // in_proj t-half (warp-uniform)

    // ---- embedding gather ----
    for (int i = tid; i < LSEQ*DMODEL; i += 128) {
        int t = i >> 6, d = i & 63;
        s_x[i] = embedding[input_ids[b*LSEQ + t]*DMODEL + d];
    }

    for (int l = 0; l < NLAYER; ++l) {
        const int wb = s*NLAYER + l;
        __syncthreads();

        // ---- rmsnorm -> xnT (transposed, zero-padded t>=41) ----
        {
            float nw0 = norm_w[wb*DMODEL + lane];
            float nw1 = norm_w[wb*DMODEL + 32 + lane];
            for (int t = warp; t < TPAD; t += 4) {
                if (t < LSEQ) {
                    float v0 = s_x[t*DMODEL + lane];
                    float v1 = s_x[t*DMODEL + 32 + lane];
                    float ss = v0*v0 + v1*v1;
                    #pragma unroll
                    for (int o = 16; o; o >>= 1) ss += __shfl_xor_sync(0xffffffffu, ss, o);
                    float inv = rsqrtf(ss * (1.f/64.f) + 1e-5f);
                    s_xnT[lane*TP + t]      = v0 * inv * nw0;
                    s_xnT[(lane+32)*TP + t] = v1 * inv * nw1;
                } else {
                    s_xnT[lane*TP + t] = 0.f;
                    s_xnT[(lane+32)*TP + t] = 0.f;
                }
            }
        }

        // ---- in_proj matmul: [41x64] @ [64x256]
        // thread (cI,hI) computes u cols {cI, cI+64} and res cols {cI+128, cI+192}
        // over t-pairs [hI*11, hI*11+11). res stays in registers until gating.
        ULL ar0[11], ar1[11];
        {
            ULL au0[11], au1[11];
            #pragma unroll
            for (int k = 0; k < 11; ++k) { au0[k]=0ull; au1[k]=0ull; ar0[k]=0ull; ar1[k]=0ull; }
            const float* ipw = in_proj + (size_t)wb * DMODEL * 2 * DINNER;
            for (int dc = 0; dc < 4; ++dc) {
                __syncthreads();
                #pragma unroll
                for (int i = tid*4; i < 4096; i += 512)
                    *(float4*)&s_w[i] = *(const float4*)&ipw[dc*4096 + i];
                __syncthreads();
                #pragma unroll
                for (int dd = 0; dd < 16; ++dd) {
                    const int d = dc*16 + dd;
                    ULL wu0 = pack2(s_w[dd*256 + cI]);
                    ULL wu1 = pack2(s_w[dd*256 + 64 + cI]);
                    ULL wr0 = pack2(s_w[dd*256 + 128 + cI]);
                    ULL wr1 = pack2(s_w[dd*256 + 192 + cI]);
                    const ULL* xr = (const ULL*)&s_xnT[d*TP] + hI*11;
                    #pragma unroll
                    for (int k = 0; k < 11; ++k) {
                        ULL xv = xr[k];
                        ffma2(au0[k], xv, wu0);
                        ffma2(au1[k], xv, wu1);
                        ffma2(ar0[k], xv, wr0);
                        ffma2(ar1[k], xv, wr1);
                    }
                }
            }
            // store pre-conv u to uT rows cI and cI+64 (this thread's t-half)
            ULL* up0 = (ULL*)&s_uT[cI*TP] + hI*11;
            ULL* up1 = (ULL*)&s_uT[(cI+64)*TP] + hI*11;
            #pragma unroll
            for (int k = 0; k < 11; ++k) { up0[k] = au0[k]; up1[k] = au1[k]; }
        }
        __syncthreads();

        // ---- causal conv(K=4)+bias+silu, thread = channel tid ----
        {
            float ul[TPAD];
            const ULL* ur = (const ULL*)&s_uT[tid*TP];
            #pragma unroll
            for (int k = 0; k < NPAIR; ++k) unpack2(ur[k], ul[2*k], ul[2*k+1]);
            const float* cw = conv_w + (size_t)(wb*DINNER + tid)*KCONV;
            float c0 = cw[0], c1 = cw[1], c2 = cw[2], c3 = cw[3];
            float cb = conv_b[wb*DINNER + tid];
            #pragma unroll
            for (int t = 0; t < LSEQ; ++t) {
                float a = ul[t]*c3 + cb;
                if (t >= 1) a += ul[t-1]*c2;
                if (t >= 2) a += ul[t-2]*c1;
                if (t >= 3) a += ul[t-3]*c0;
                s_uT[tid*TP + t] = siluf(a);
            }
            #pragma unroll
            for (int t = LSEQ; t < TPAD; ++t) s_uT[tid*TP + t] = 0.f;
        }

        // ---- x_proj matmul: dbl[41][36] = u @ xp[128x36] ----
        {
            __syncthreads();
            const float* xpw = x_proj + (size_t)wb * DINNER * 36;
            #pragma unroll
            for (int i = tid*4; i < DINNER*36; i += 512)
                *(float4*)&s_w[i] = *(const float4*)&xpw[i];
            __syncthreads();
            const int jj = tid % 36;
            const int g  = tid / 36;
            if (g < 3) {
                const int t0 = g * 14;
                ULL acc2[7];
                #pragma unroll
                for (int k = 0; k < 7; ++k) acc2[k] = 0ull;
                for (int d = 0; d < DINNER; ++d) {
                    ULL w2 = pack2(s_w[d*36 + jj]);
                    const ULL* ur = (const ULL*)&s_uT[d*TP + t0];
                    #pragma unroll
                    for (int k = 0; k < 7; ++k) ffma2(acc2[k], ur[k], w2);
                }
                #pragma unroll
                for (int k = 0; k < 7; ++k) {
                    float a0, a1; unpack2(acc2[k], a0, a1);
                    int t = t0 + 2*k;
                    if (t < LSEQ)   s_dbl[t*36 + jj]     = a0;
                    if (t+1 < LSEQ) s_dbl[(t+1)*36 + jj] = a1;
                }
            }
        }

        // ---- selective scan (thread = channel, h[16] in regs), dbl via float4 ----
        {
            float dw0 = dt_w[(wb*DTRANK+0)*DINNER + tid];
            float dw1 = dt_w[(wb*DTRANK+1)*DINNER + tid];
            float dw2 = dt_w[(wb*DTRANK+2)*DINNER + tid];
            float dw3 = dt_w[(wb*DTRANK+3)*DINNER + tid];
            float dtbv = dt_b[wb*DINNER + tid];
            float dpv  = Dp[wb*DINNER + tid];
            float Av[NSTATE];
            const float* al = A_log + (size_t)(wb*DINNER + tid)*NSTATE;
            #pragma unroll
            for (int n = 0; n < NSTATE; ++n) Av[n] = -__expf(al[n]);
            __syncthreads();
            float h[NSTATE];
            #pragma unroll
            for (int n = 0; n < NSTATE; ++n) h[n] = 0.f;
            for (int t = 0; t < LSEQ; ++t) {
                const float4* dr4 = (const float4*)&s_dbl[t*36];
                float4 qd = dr4[0];
                float xr = qd.x*dw0 + qd.y*dw1 + qd.z*dw2 + qd.w*dw3 + dtbv;
                float dt = (xr > 15.f) ? xr : log1pf(__expf(xr));
                float ut = s_uT[tid*TP + t];
                float dtu = dt * ut;
                float4 b0 = dr4[1], b1 = dr4[2], b2 = dr4[3], b3 = dr4[4];
                float4 q0 = dr4[5], q1 = dr4[6], q2 = dr4[7], q3 = dr4[8];
                float Bv[16] = {b0.x,b0.y,b0.z,b0.w, b1.x,b1.y,b1.z,b1.w,
                                b2.x,b2.y,b2.z,b2.w, b3.x,b3.y,b3.z,b3.w};
                float Cv[16] = {q0.x,q0.y,q0.z,q0.w, q1.x,q1.y,q1.z,q1.w,
                                q2.x,q2.y,q2.z,q2.w, q3.x,q3.y,q3.z,q3.w};
                float y = 0.f;
                #pragma unroll
                for (int n = 0; n < NSTATE; ++n) {
                    float dA = __expf(dt * Av[n]);
                    h[n] = dA*h[n] + dtu*Bv[n];
                    y += h[n]*Cv[n];
                }
                s_uT[tid*TP + t] = y + ut*dpv;   // ungated z
            }
        }
        __syncthreads();

        // ---- gate z with silu(res) held in registers (thread owns rows cI, cI+64 for its t-half) ----
        {
            ULL* z0 = (ULL*)&s_uT[cI*TP] + hI*11;
            ULL* z1 = (ULL*)&s_uT[(cI+64)*TP] + hI*11;
            #pragma unroll
            for (int k = 0; k < 11; ++k) {
                float r0, r1; unpack2(ar0[k], r0, r1);
                z0[k] = mul2(z0[k], pack2f(siluf(r0), siluf(r1)));
                float r2, r3; unpack2(ar1[k], r2, r3);
                z1[k] = mul2(z1[k], pack2f(siluf(r2), siluf(r3)));
            }
        }

        // ---- out_proj matmul + residual add: x += g @ op[128x64]
        // thread: cols {col, col+32}, warp t-quarter (pairs base..base+np) ----
        {
            const float* opw = out_proj + (size_t)wb * DINNER * DMODEL;
            const int col = tid & 31;
            const int base = (warp==0) ? 0 : (warp==1) ? 6 : (warp==2) ? 12 : 17;
            const int np   = (warp < 2) ? 6 : 5;
            ULL a0[6], a1[6];
            #pragma unroll
            for (int k = 0; k < 6; ++k) { a0[k]=0ull; a1[k]=0ull; }
            for (int dc = 0; dc < 2; ++dc) {
                __syncthreads();
                #pragma unroll
                for (int i = tid*4; i < 4096; i += 512)
                    *(float4*)&s_w[i] = *(const float4*)&opw[dc*4096 + i];
                __syncthreads();
                #pragma unroll
                for (int dd = 0; dd < 64; ++dd) {
                    const int d = dc*64 + dd;
                    ULL w0 = pack2(s_w[dd*64 + col]);
                    ULL w1 = pack2(s_w[dd*64 + 32 + col]);
                    const ULL* gr = (const ULL*)&s_uT[d*TP] + base;
                    #pragma unroll
                    for (int k = 0; k < 6; ++k) {   // k==5 for np==5 reads garbage, discarded
                        ULL gv = gr[k];
                        ffma2(a0[k], gv, w0);
                        ffma2(a1[k], gv, w1);
                    }
                }
            }
            __syncthreads();
            #pragma unroll
            for (int k = 0; k < 6; ++k) {
                if (k < np) {
                    int t = (base + k)*2;
                    float v0, v1; unpack2(a0[k], v0, v1);
                    float w0, w1; unpack2(a1[k], w0, w1);
                    if (t < LSEQ)   { s_x[t*DMODEL + col] += v0; s_x[t*DMODEL + 32 + col] += w0; }
                    if (t+1 < LSEQ) { s_x[(t+1)*DMODEL + col] += v1; s_x[(t+1)*DMODEL + 32 + col] += w1; }
                }
            }
        }
    }

    // ---- final rmsnorm (norm_f_w) + store stack output ----
    __syncthreads();
    {
        float nw0 = norm_f_w[lane], nw1 = norm_f_w[32 + lane];
        for (int t = warp; t < LSEQ; t += 4) {
            float v0 = s_x[t*DMODEL + lane];
            float v1 = s_x[t*DMODEL + 32 + lane];
            float ss = v0*v0 + v1*v1;
            #pragma unroll
            for (int o = 16; o; o >>= 1) ss += __shfl_xor_sync(0xffffffffu, ss, o);
            float inv = rsqrtf(ss * (1.f/64.f) + 1e-5f);
            float* dst = g_stack + ((size_t)(s*BATCH + b)*LSEQ + t)*DMODEL;
            dst[lane]      = v0 * inv * nw0;
            dst[lane + 32] = v1 * inv * nw1;
        }
    }
}

// ---- head GEMM: h1 = relu(fused[512x2624] @ W1[2624x384] + b1), fused = softmax(fw)·stacks ----
__global__ void __launch_bounds__(128)
head_gemm1(const float* __restrict__ fusion_w, const float* __restrict__ W1,
           const float* __restrict__ b1)
{
    __shared__ float As[32][33];
    __shared__ float Ws[32][64];
    const int tid = threadIdx.x;
    const int rb = blockIdx.x, cb = blockIdx.y;
    float f0 = fusion_w[0], f1 = fusion_w[1], f2 = fusion_w[2];
    float m = fmaxf(f0, fmaxf(f1, f2));
    float e0 = expf(f0-m), e1 = expf(f1-m), e2 = expf(f2-m);
    float inv = 1.f/(e0+e1+e2);
    e0 *= inv; e1 *= inv; e2 *= inv;
    const int tx = tid & 15, ty = tid >> 4;
    ULL acc2[4][2];
    #pragma unroll
    for (int r = 0; r < 4; ++r) { acc2[r][0] = 0ull; acc2[r][1] = 0ull; }
    const int KT = LSEQ*DMODEL;             // 2624 = 82*32
    const size_t SS = (size_t)BATCH * KT;   // stack stride
    for (int kc = 0; kc < KT/32; ++kc) {
        __syncthreads();
        #pragma unroll
        for (int i = tid; i < 1024; i += 128) {
            int r = i >> 5, kk = i & 31;
            size_t base = (size_t)(rb*32 + r)*KT + kc*32 + kk;
            As[r][kk] = e0*g_stack[base] + e1*g_stack[base + SS] + e2*g_stack[base + 2*SS];
        }
        #pragma unroll
        for (int i = tid; i < 2048; i += 128) {
            int kk = i >> 6, j = i & 63;
            Ws[kk][j] = W1[(size_t)(kc*32 + kk)*384 + cb*64 + j];
        }
        __syncthreads();
        #pragma unroll
        for (int kk = 0; kk < 32; ++kk) {
            const ULL* wp = (const ULL*)&Ws[kk][tx*4];
            ULL w0 = wp[0], w1 = wp[1];
            ULL a0 = pack2(As[ty*4+0][kk]);
            ULL a1 = pack2(As[ty*4+1][kk]);
            ULL a2 = pack2(As[ty*4+2][kk]);
            ULL a3 = pack2(As[ty*4+3][kk]);
            ffma2(acc2[0][0], a0, w0); ffma2(acc2[0][1], a0, w1);
            ffma2(acc2[1][0], a1, w0); ffma2(acc2[1][1], a1, w1);
            ffma2(acc2[2][0], a2, w0); ffma2(acc2[2][1], a2, w1);
            ffma2(acc2[3][0], a3, w0); ffma2(acc2[3][1], a3, w1);
        }
    }
    #pragma unroll
    for (int r = 0; r < 4; ++r) {
        int row = rb*32 + ty*4 + r;
        #pragma unroll
        for (int p = 0; p < 2; ++p) {
            float v0, v1; unpack2(acc2[r][p], v0, v1);
            int colg = cb*64 + tx*4 + p*2;
            g_h1[(size_t)row*384 + colg]     = fmaxf(v0 + b1[colg], 0.f);
            g_h1[(size_t)row*384 + colg + 1] = fmaxf(v1 + b1[colg+1], 0.f);
        }
    }
}

// ---- final tail: h2 = relu(h1 @ W2 + b2); logit = h2 @ W3 + b3; sigmoid ----
__global__ void head_final(const float* __restrict__ W2, const float* __restrict__ b2,
                           const float* __restrict__ W3, const float* __restrict__ b3,
                           float* __restrict__ out)
{
    const int warp = threadIdx.x >> 5, lane = threadIdx.x & 31;
    const int b = blockIdx.x*4 + warp;
    if (b >= BATCH) return;
    const int j = lane & 15;
    const float* hr = g_h1 + (size_t)b*384;
    float a0 = 0.f, a1 = 0.f, a2 = 0.f, a3 = 0.f;
    for (int i = 0; i < 384; i += 4) {
        a0 += hr[i]   * W2[(i  )*16 + j];
        a1 += hr[i+1] * W2[(i+1)*16 + j];
        a2 += hr[i+2] * W2[(i+2)*16 + j];
        a3 += hr[i+3] * W2[(i+3)*16 + j];
    }
    float h2 = fmaxf(a0 + a1 + a2 + a3 + b2[j], 0.f);
    float p = (lane < 16) ? h2 * W3[j] : 0.f;
    #pragma unroll
    for (int o = 16; o; o >>= 1) p += __shfl_xor_sync(0xffffffffu, p, o);
    if (lane == 0) out[b] = 1.f / (1.f + expf(-(p + b3[0])));
}

extern "C" void kernel_launch(void* const* d_in, const int* in_sizes, int n_in,
                              void* d_out, int out_size) {
    const int*   input_ids = (const int*)d_in[0];
    const float* embedding = (const float*)d_in[1];
    const float* in_proj   = (const float*)d_in[2];
    const float* conv_w    = (const float*)d_in[3];
    const float* conv_b    = (const float*)d_in[4];
    const float* x_proj    = (const float*)d_in[5];
    const float* dt_w      = (const float*)d_in[6];
    const float* dt_b      = (const float*)d_in[7];
    const float* A_log     = (const float*)d_in[8];
    const float* Dp        = (const float*)d_in[9];
    const float* out_proj  = (const float*)d_in[10];
    const float* norm_w    = (const float*)d_in[11];
    const float* norm_f_w  = (const float*)d_in[12];
    const float* fusion_w  = (const float*)d_in[13];
    const float* W1        = (const float*)d_in[14];
    const float* b1        = (const float*)d_in[15];
    const float* W2        = (const float*)d_in[16];
    const float* b2        = (const float*)d_in[17];
    const float* W3        = (const float*)d_in[18];
    const float* b3        = (const float*)d_in[19];
    float* out = (float*)d_out;
    (void)in_sizes; (void)n_in; (void)out_size;

    const int smemA = 17540 * 4;  // 70160 bytes -> 3 CTAs/SM
    cudaFuncSetAttribute(mamba_stack_kernel,
                         cudaFuncAttributeMaxDynamicSharedMemorySize, smemA);
    mamba_stack_kernel<<<dim3(BATCH, NSTACK), 128, smemA>>>(
        input_ids, embedding, in_proj, conv_w, conv_b, x_proj, dt_w, dt_b,
        A_log, Dp, out_proj, norm_w, norm_f_w);
    head_gemm1<<<dim3(16, 6), 128>>>(fusion_w, W1, b1);
    head_final<<<128, 128>>>(W2, b2, W3, b3, out);
}